// round 4
// baseline (speedup 1.0000x reference)
#include <cuda_runtime.h>
#include <cuda_bf16.h>
#include <cstdint>

#define B       128
#define T       256
#define H       1024
#define NG      4096
#define THREADS 512
#define CTAS    128
#define JPC     8
#define KCH     64          // k per chunk
#define NCHUNK  16

// ---- persistent device state ----
__device__ __nv_bfloat16 g_hhi[2][B * H];
__device__ __nv_bfloat16 g_hlo[2][B * H];
__device__ unsigned int g_bar_arrive = 0;
__device__ volatile unsigned int g_bar_gen = 0;

// ---- SMEM layout (bytes) ----
#define U_RSTRIDE 2064      // 32 n-rows x 1024 k bf16, padded (conflict-free ldmatrix)
#define OFF_UHI 0
#define OFF_ULO 66048
#define A_RSTRIDE 144       // 128 rows x 64 k bf16 + 16B pad
#define A_TILE  18432
#define OFF_A   132096      // slot s: hi = OFF_A + s*36864, lo = +18432 (2 slots)
#define OFF_SSM 205824      // seq staging 128*4 f32 = 2048
#define OFF_W   207872      // 4*32 f32
#define OFF_BS  208384      // 32 f32
#define SMEM_TOTAL 208512
// gate-exchange buffer (8KB) aliases slot 0 (chunk 14 data, dead by epilogue)

__device__ __forceinline__ uint32_t smem_u32(const void* p) {
    uint32_t a;
    asm("{ .reg .u64 t; cvta.to.shared.u64 t, %1; cvt.u32.u64 %0, t; }"
        : "=r"(a) : "l"(p));
    return a;
}

#define CP16(dst, src) asm volatile("cp.async.cg.shared.global [%0], [%1], 16;" :: "r"(dst), "l"(src))
#define CPCOMMIT()     asm volatile("cp.async.commit_group;" ::: "memory")
#define CPWAIT(n)      asm volatile("cp.async.wait_group %0;" :: "n"(n) : "memory")

#define LDSM_X4(r0, r1, r2, r3, a) \
    asm volatile("ldmatrix.sync.aligned.m8n8.x4.shared.b16 {%0,%1,%2,%3}, [%4];" \
                 : "=r"(r0), "=r"(r1), "=r"(r2), "=r"(r3) : "r"(a))

#define MMA_BF16(d, a0, a1, a2, a3, b0, b1) \
    asm volatile("mma.sync.aligned.m16n8k16.row.col.f32.bf16.bf16.f32 " \
                 "{%0,%1,%2,%3}, {%4,%5,%6,%7}, {%8,%9}, {%0,%1,%2,%3};" \
                 : "+f"((d)[0]), "+f"((d)[1]), "+f"((d)[2]), "+f"((d)[3]) \
                 : "r"(a0), "r"(a1), "r"(a2), "r"(a3), "r"(b0), "r"(b1))

__device__ __forceinline__ void grid_barrier() {
    __syncthreads();
    __threadfence();
    if (threadIdx.x == 0) {
        unsigned int gen = g_bar_gen;
        if (atomicAdd(&g_bar_arrive, 1u) == CTAS - 1) {
            g_bar_arrive = 0;
            __threadfence();
            g_bar_gen = gen + 1;
        } else {
            while (g_bar_gen == gen) { }
        }
    }
    __syncthreads();
}

// stage one 64-k chunk of h (hi + lo) into an A slot (512 threads)
__device__ __forceinline__ void load_chunk(uint32_t ahib, uint32_t alob,
                                           const __nv_bfloat16* __restrict__ hhi,
                                           const __nv_bfloat16* __restrict__ hlo,
                                           int c, int tid) {
#pragma unroll
    for (int i = 0; i < 2; ++i) {
        int seg = tid + i * THREADS;          // 1024 16B segs per tile
        int row = seg >> 3, sc = seg & 7;
        uint32_t d = row * A_RSTRIDE + sc * 16;
        CP16(ahib + d, hhi + row * H + c * KCH + sc * 8);
        CP16(alob + d, hlo + row * H + c * KCH + sc * 8);
    }
    CPCOMMIT();
}

__global__ void __launch_bounds__(THREADS, 1)
lstm_hmma_kernel(const float* __restrict__ seq,
                 const float* __restrict__ W,
                 const float* __restrict__ U,
                 const float* __restrict__ bias,
                 float* __restrict__ out,
                 int write_extras)
{
    extern __shared__ __align__(1024) uint8_t smem[];
    const uint32_t sbase = smem_u32(smem);
    const int tid = threadIdx.x;
    const int wid = tid >> 5;
    const int lid = tid & 31;
    const int wg  = wid >> 3;         // 0: gates i,f   1: gates g,o
    const int wm  = wid & 7;          // M-row group (rows 16*wm..16*wm+15)
    const int cta = blockIdx.x;
    const int j0  = cta * JPC;

    float* ssm = (float*)(smem + OFF_SSM);
    float* Wsl = (float*)(smem + OFF_W);
    float* bsl = (float*)(smem + OFF_BS);
    float4* zsm4 = (float4*)(smem + OFF_A);   // aliases slot 0 (safe at epilogue)

    // ---------------- prologue ----------------
    for (int idx = tid; idx < 32 * H; idx += THREADS) {
        int k = idx >> 5, n = idx & 31;
        int gcol = ((n >> 3) << 10) + j0 + (n & 7);
        float v = U[(size_t)k * NG + gcol];
        __nv_bfloat16 hi = __float2bfloat16(v);
        __nv_bfloat16 lo = __float2bfloat16(v - __bfloat162float(hi));
        *(__nv_bfloat16*)(smem + OFF_UHI + n * U_RSTRIDE + k * 2) = hi;
        *(__nv_bfloat16*)(smem + OFF_ULO + n * U_RSTRIDE + k * 2) = lo;
    }
    if (tid < 4 * 32) {
        int f = tid >> 5, cc = tid & 31;
        Wsl[tid] = W[f * NG + ((cc >> 3) << 10) + j0 + (cc & 7)];
    }
    if (tid < 32)
        bsl[tid] = bias[((tid >> 3) << 10) + j0 + (tid & 7)];
    for (int idx = tid; idx < B * JPC; idx += THREADS) {
        int b = idx >> 3, jj = idx & 7;
        g_hhi[0][b * H + j0 + jj] = __float2bfloat16(0.0f);
        g_hlo[0][b * H + j0 + jj] = __float2bfloat16(0.0f);
    }
    grid_barrier();

    // ---- per-lane fragment geometry ----
    const int lr  = lid & 7;
    const int grp = lid >> 3;
    const uint32_t aoff = (uint32_t)((16 * wm + (grp & 1) * 8 + lr) * A_RSTRIDE + (grp >> 1) * 16);
    // B: group 0 reads n-rows 0-15, group 1 reads n-rows 16-31
    const uint32_t boff = (uint32_t)(((grp >> 1) * 8 + lr + wg * 16) * U_RSTRIDE + (grp & 1) * 16);
    const uint32_t uhib = sbase + OFF_UHI;
    const uint32_t ulob = sbase + OFF_ULO;

    uint32_t aHi[2], aLo[2];
#pragma unroll
    for (int s = 0; s < 2; ++s) {
        aHi[s] = sbase + OFF_A + s * (2 * A_TILE);
        aLo[s] = aHi[s] + A_TILE;
    }

    const int rq = lid >> 2;            // 0..7
    const int jp = (lid & 3) * 2;       // jj pair base

    float c_reg[4];
#pragma unroll
    for (int q = 0; q < 4; ++q) c_reg[q] = 0.0f;

    const size_t OFF_HL = (size_t)B * T * H;
    const size_t OFF_CL = OFF_HL + (size_t)B * H;

    for (int t = 0; t < T; ++t) {
        const int r = t & 1, wb = r ^ 1;
        const __nv_bfloat16* hhi = g_hhi[r];
        const __nv_bfloat16* hlo = g_hlo[r];

        if (tid < B) {
            float4 s4 = __ldg((const float4*)seq + ((size_t)tid * T + t));
            ssm[tid * 4 + 0] = s4.x; ssm[tid * 4 + 1] = s4.y;
            ssm[tid * 4 + 2] = s4.z; ssm[tid * 4 + 3] = s4.w;
        }

        // 3 independent accumulator sets (hh, hl, lh), 2 n-tiles each
        float ahh[2][4], ahl[2][4], alh[2][4];
#pragma unroll
        for (int n = 0; n < 2; ++n)
#pragma unroll
            for (int q = 0; q < 4; ++q) { ahh[n][q] = 0.f; ahl[n][q] = 0.f; alh[n][q] = 0.f; }

        // preload chunk 0 into slot 0
        load_chunk(aHi[0], aLo[0], hhi, hlo, 0, tid);

        for (int c = 0; c < NCHUNK; ++c) {
            const int sl = c & 1;
            CPWAIT(0);           // own copies of chunk c complete
            __syncthreads();     // chunk c visible to all; all prior-chunk reads done
            if (c + 1 < NCHUNK)  // overlaps with this chunk's MMAs
                load_chunk(aHi[sl ^ 1], aLo[sl ^ 1], hhi, hlo, c + 1, tid);

#pragma unroll
            for (int q = 0; q < 4; ++q) {
                const uint32_t kb = (uint32_t)(c * 128 + q * 32);
                uint32_t ah0, ah1, ah2, ah3, al0, al1, al2, al3;
                LDSM_X4(ah0, ah1, ah2, ah3, aHi[sl] + aoff + q * 32);
                LDSM_X4(al0, al1, al2, al3, aLo[sl] + aoff + q * 32);
                uint32_t bh[4], bl[4];
                LDSM_X4(bh[0], bh[1], bh[2], bh[3], uhib + boff + kb);
                LDSM_X4(bl[0], bl[1], bl[2], bl[3], ulob + boff + kb);
                MMA_BF16(ahh[0], ah0, ah1, ah2, ah3, bh[0], bh[1]);
                MMA_BF16(ahh[1], ah0, ah1, ah2, ah3, bh[2], bh[3]);
                MMA_BF16(ahl[0], ah0, ah1, ah2, ah3, bl[0], bl[1]);
                MMA_BF16(ahl[1], ah0, ah1, ah2, ah3, bl[2], bl[3]);
                MMA_BF16(alh[0], al0, al1, al2, al3, bh[0], bh[1]);
                MMA_BF16(alh[1], al0, al1, al2, al3, bh[2], bh[3]);
            }
        }

        // ---- combine passes ----
        float zs[2][4];
#pragma unroll
        for (int n = 0; n < 2; ++n)
#pragma unroll
            for (int q = 0; q < 4; ++q)
                zs[n][q] = ahh[n][q] + ahl[n][q] + alh[n][q];

        // ---- gate exchange: wg1 (g,o) -> SMEM ----
        // note: zsm aliases slot 0 (last held chunk 14; all reads finished —
        // every warp passed chunk-15's sync before any warp reaches here)
        if (wg == 1) {
            zsm4[(tid - 256) * 2 + 0] = make_float4(zs[0][0], zs[0][1], zs[0][2], zs[0][3]);
            zsm4[(tid - 256) * 2 + 1] = make_float4(zs[1][0], zs[1][1], zs[1][2], zs[1][3]);
        }
        __syncthreads();

        // ---- epilogue on wg0 (has i,f; reads g,o) ----
        if (wg == 0) {
            float4 zg4 = zsm4[tid * 2 + 0];   // gate g, cells 0..3
            float4 zo4 = zsm4[tid * 2 + 1];   // gate o, cells 0..3
            const float zg_[4] = { zg4.x, zg4.y, zg4.z, zg4.w };
            const float zo_[4] = { zo4.x, zo4.y, zo4.z, zo4.w };
#pragma unroll
            for (int k = 0; k < 4; ++k) {
                const int b  = 16 * wm + rq + ((k >> 1) << 3);
                const int jj = jp + (k & 1);
                const float s0 = ssm[b * 4 + 0], s1 = ssm[b * 4 + 1];
                const float s2 = ssm[b * 4 + 2], s3 = ssm[b * 4 + 3];
                float z[4] = { zs[0][k], zs[1][k], zg_[k], zo_[k] };
#pragma unroll
                for (int g = 0; g < 4; ++g) {
                    const int cc = g * 8 + jj;
                    z[g] += bsl[cc] + s0 * Wsl[cc] + s1 * Wsl[32 + cc]
                          + s2 * Wsl[64 + cc] + s3 * Wsl[96 + cc];
                }
                float ig = 1.0f / (1.0f + __expf(-z[0]));
                float fg = 1.0f / (1.0f + __expf(-z[1]));
                float gg = fmaxf(z[2], 0.0f);
                float og = 1.0f / (1.0f + __expf(-z[3]));
                float cn = fg * c_reg[k] + ig * gg;
                c_reg[k] = cn;
                float hv = og * fmaxf(cn, 0.0f);

                out[((size_t)b * T + t) * H + j0 + jj] = hv;
                __nv_bfloat16 hh = __float2bfloat16(hv);
                __nv_bfloat16 hl = __float2bfloat16(hv - __bfloat162float(hh));
                g_hhi[wb][(size_t)b * H + j0 + jj] = hh;
                g_hlo[wb][(size_t)b * H + j0 + jj] = hl;

                if (write_extras && t == T - 1) {
                    out[OFF_HL + (size_t)b * H + j0 + jj] = hv;
                    out[OFF_CL + (size_t)b * H + j0 + jj] = cn;
                }
            }
        }
        grid_barrier();   // h complete chip-wide before next step's loads
    }
}

extern "C" void kernel_launch(void* const* d_in, const int* in_sizes, int n_in,
                              void* d_out, int out_size)
{
    const float* seq  = (const float*)d_in[0];   // [128,256,4]
    const float* W    = (const float*)d_in[1];   // [4,4096]
    const float* U    = (const float*)d_in[2];   // [1024,4096]
    const float* bias = (const float*)d_in[3];   // [4096]
    float* out = (float*)d_out;

    long long need = (long long)B * T * H + 2LL * B * H;
    int write_extras = ((long long)out_size >= need) ? 1 : 0;

    cudaFuncSetAttribute(lstm_hmma_kernel,
                         cudaFuncAttributeMaxDynamicSharedMemorySize, SMEM_TOTAL);
    lstm_hmma_kernel<<<CTAS, THREADS, SMEM_TOTAL>>>(seq, W, U, bias, out,
                                                    write_extras);
}

// round 5
// speedup vs baseline: 1.1156x; 1.1156x over previous
#include <cuda_runtime.h>
#include <cuda_bf16.h>
#include <cstdint>

#define B       128
#define T       256
#define H       1024
#define NG      4096
#define THREADS 256
#define CTAS    128
#define JPC     8
#define NCHUNK  16          // 16 chunks of k=64

// ---- persistent device state ----
// h in mma-A-fragment layout: [buf][chunk*1024 + qs*256 + m*32 + lane] (uint4 = a0..a3)
__device__ uint4 g_hfH[2][NCHUNK * 1024];
__device__ uint4 g_hfL[2][NCHUNK * 1024];
__device__ unsigned int g_bar_arrive = 0;
__device__ volatile unsigned int g_bar_gen = 0;

// ---- SMEM layout (bytes) ----
#define U_RSTRIDE 2064      // U^T rows padded -> conflict-free ldmatrix
#define OFF_UHI 0           // 66048
#define OFF_ULO 66048       // 66048
#define OFF_A   132096      // 2 slots x 32768 (AH 16K + AL 16K), frag layout
#define OFF_ZX  197632      // 16384  z exchange (k-half reduction)
#define OFF_W   214016      // 4*32 f32
#define OFF_BS  214528      // 32 f32
#define SMEM_TOTAL 214656

__device__ __forceinline__ uint32_t smem_u32(const void* p) {
    uint32_t a;
    asm("{ .reg .u64 t; cvta.to.shared.u64 t, %1; cvt.u32.u64 %0, t; }"
        : "=r"(a) : "l"(p));
    return a;
}

#define CP16(dst, src) asm volatile("cp.async.cg.shared.global [%0], [%1], 16;" :: "r"(dst), "l"(src))
#define CPCOMMIT()     asm volatile("cp.async.commit_group;" ::: "memory")
#define CPWAIT0()      asm volatile("cp.async.wait_group 0;" ::: "memory")

#define LDSM_X4(r0, r1, r2, r3, a) \
    asm volatile("ldmatrix.sync.aligned.m8n8.x4.shared.b16 {%0,%1,%2,%3}, [%4];" \
                 : "=r"(r0), "=r"(r1), "=r"(r2), "=r"(r3) : "r"(a))

#define LDS128(v, a) \
    asm volatile("ld.shared.v4.u32 {%0,%1,%2,%3}, [%4];" \
                 : "=r"((v).x), "=r"((v).y), "=r"((v).z), "=r"((v).w) : "r"(a))

#define MMA_BF16(d, a0, a1, a2, a3, b0, b1) \
    asm volatile("mma.sync.aligned.m16n8k16.row.col.f32.bf16.bf16.f32 " \
                 "{%0,%1,%2,%3}, {%4,%5,%6,%7}, {%8,%9}, {%0,%1,%2,%3};" \
                 : "+f"((d)[0]), "+f"((d)[1]), "+f"((d)[2]), "+f"((d)[3]) \
                 : "r"(a0), "r"(a1), "r"(a2), "r"(a3), "r"(b0), "r"(b1))

__device__ __forceinline__ void grid_barrier() {
    __syncthreads();
    __threadfence();
    if (threadIdx.x == 0) {
        unsigned int gen = g_bar_gen;
        if (atomicAdd(&g_bar_arrive, 1u) == CTAS - 1) {
            g_bar_arrive = 0;
            __threadfence();
            g_bar_gen = gen + 1;
        } else {
            while (g_bar_gen == gen) { }
        }
    }
    __syncthreads();
}

__device__ __forceinline__ uint32_t packbf(__nv_bfloat16 a, __nv_bfloat16 b) {
    return (uint32_t)__bfloat16_as_ushort(a) | ((uint32_t)__bfloat16_as_ushort(b) << 16);
}

// stage one chunk (1024 uint4 hi + 1024 lo) into a slot: linear coalesced copy
__device__ __forceinline__ void stage(uint32_t slot, const uint4* __restrict__ HH,
                                      const uint4* __restrict__ HL, int c, int tid) {
#pragma unroll
    for (int i = 0; i < 4; ++i) {
        int e = tid + i * THREADS;
        CP16(slot + e * 16, HH + c * 1024 + e);
        CP16(slot + 16384 + e * 16, HL + c * 1024 + e);
    }
    CPCOMMIT();
}

__global__ void __launch_bounds__(THREADS, 1)
lstm_frag_kernel(const float* __restrict__ seq,
                 const float* __restrict__ W,
                 const float* __restrict__ U,
                 const float* __restrict__ bias,
                 float* __restrict__ out,
                 int write_extras)
{
    extern __shared__ __align__(1024) uint8_t smem[];
    const uint32_t sbase = smem_u32(smem);
    const int tid = threadIdx.x;
    const int wid = tid >> 5;
    const int lid = tid & 31;
    const int ms  = wid & 3;          // m-group: mtiles 2ms, 2ms+1
    const int kh  = wid >> 2;         // k-half of each chunk
    const int cta = blockIdx.x;
    const int j0  = cta * JPC;
    const int Kc  = cta >> 1;         // frag kstep this CTA's j-columns land in
    const int codd = cta & 1;

    float*  Wsl  = (float*)(smem + OFF_W);
    float*  bsl  = (float*)(smem + OFF_BS);
    float4* zx4  = (float4*)(smem + OFF_ZX);

    // ---------------- prologue ----------------
    // U slice -> U^T bf16 hi/lo (row n = gate*8+jj, k contiguous)
    for (int idx = tid; idx < 32 * H; idx += THREADS) {
        int k = idx >> 5, n = idx & 31;
        int gcol = ((n >> 3) << 10) + j0 + (n & 7);
        float v = U[(size_t)k * NG + gcol];
        __nv_bfloat16 hi = __float2bfloat16(v);
        __nv_bfloat16 lo = __float2bfloat16(v - __bfloat162float(hi));
        *(__nv_bfloat16*)(smem + OFF_UHI + n * U_RSTRIDE + k * 2) = hi;
        *(__nv_bfloat16*)(smem + OFF_ULO + n * U_RSTRIDE + k * 2) = lo;
    }
    if (tid < 4 * 32) {
        int f = tid >> 5, cc = tid & 31;
        Wsl[tid] = W[f * NG + ((cc >> 3) << 10) + j0 + (cc & 7)];
    }
    if (tid < 32)
        bsl[tid] = bias[((tid >> 3) << 10) + j0 + (tid & 7)];
    // zero-init this CTA's h-frag region in buf 0 (its 8B half of each elem)
    {
        int m = tid >> 5, lane = tid & 31;                    // tid covers 8*32
        int elem = (Kc * 8 + m) * 32 + lane;                   // Kc chunk index: global kstep
        // global elem index: kstep Kc -> chunk c0 = Kc>>2, qs = Kc&3
        int gidx = (Kc >> 2) * 1024 + (Kc & 3) * 256 + m * 32 + lane;
        (void)elem;
        ((uint2*)&g_hfH[0][gidx])[codd] = make_uint2(0u, 0u);
        ((uint2*)&g_hfL[0][gidx])[codd] = make_uint2(0u, 0u);
    }
    grid_barrier();

    // ---- B ldmatrix lane geometry (R3-proven) ----
    const int lr  = lid & 7;
    const int grp = lid >> 3;
    const uint32_t boff = (uint32_t)(((grp >> 1) * 8 + lr) * U_RSTRIDE + (grp & 1) * 16);
    const uint32_t uhib = sbase + OFF_UHI;
    const uint32_t ulob = sbase + OFF_ULO;

    const int rq = lid >> 2;
    const int jp = (lid & 3) * 2;

    float c_reg[8];                   // kh0 lanes: cell state for 2 mtiles x 4 cells
#pragma unroll
    for (int q = 0; q < 8; ++q) c_reg[q] = 0.0f;

    const size_t OFF_HL = (size_t)B * T * H;
    const size_t OFF_CL = OFF_HL + (size_t)B * H;

    for (int t = 0; t < T; ++t) {
        const int rb = t & 1, wbuf = rb ^ 1;
        const uint4* HH = g_hfH[rb];
        const uint4* HL = g_hfL[rb];

        // acc: set1 = Ah*Bh, set2 = Ah*Bl + Al*Bh  [mt][n][4]
        float S1[2][4][4], S2[2][4][4];
#pragma unroll
        for (int mt = 0; mt < 2; ++mt)
#pragma unroll
            for (int n = 0; n < 4; ++n)
#pragma unroll
                for (int r = 0; r < 4; ++r) { S1[mt][n][r] = 0.f; S2[mt][n][r] = 0.f; }

        stage(sbase + OFF_A, HH, HL, 0, tid);     // preload chunk 0 -> slot 0

        for (int c = 0; c < NCHUNK; ++c) {
            CPWAIT0();
            __syncthreads();                       // chunk c visible, old slot free
            const uint32_t slot = sbase + OFF_A + (uint32_t)(c & 1) * 32768u;
            if (c + 1 < NCHUNK)                    // overlaps this chunk's MMAs
                stage(sbase + OFF_A + (uint32_t)((c + 1) & 1) * 32768u, HH, HL, c + 1, tid);

#pragma unroll
            for (int q = 0; q < 2; ++q) {
                const int K  = 4 * c + 2 * kh + q;     // global kstep
                const int qs = 2 * kh + q;             // kstep within chunk
                uint32_t bh[8], bl[8];
                LDSM_X4(bh[0], bh[1], bh[2], bh[3], uhib + boff + (uint32_t)K * 32u);
                LDSM_X4(bh[4], bh[5], bh[6], bh[7], uhib + boff + 16u * U_RSTRIDE + (uint32_t)K * 32u);
                LDSM_X4(bl[0], bl[1], bl[2], bl[3], ulob + boff + (uint32_t)K * 32u);
                LDSM_X4(bl[4], bl[5], bl[6], bl[7], ulob + boff + 16u * U_RSTRIDE + (uint32_t)K * 32u);
#pragma unroll
                for (int mt = 0; mt < 2; ++mt) {
                    const int m = 2 * ms + mt;
                    const uint32_t aaddr = slot + (uint32_t)(((qs * 8 + m) * 32 + lid) * 16);
                    uint4 AH, AL;
                    LDS128(AH, aaddr);
                    LDS128(AL, aaddr + 16384u);
#pragma unroll
                    for (int n = 0; n < 4; ++n) {
                        MMA_BF16(S1[mt][n], AH.x, AH.y, AH.z, AH.w, bh[2 * n], bh[2 * n + 1]);
                        MMA_BF16(S2[mt][n], AH.x, AH.y, AH.z, AH.w, bl[2 * n], bl[2 * n + 1]);
                        MMA_BF16(S2[mt][n], AL.x, AL.y, AL.z, AL.w, bh[2 * n], bh[2 * n + 1]);
                    }
                }
            }
        }

        // ---- reduce the two k-halves ----
        if (kh == 1) {
#pragma unroll
            for (int mt = 0; mt < 2; ++mt)
#pragma unroll
                for (int n = 0; n < 4; ++n) {
                    int zi = ((ms * 2 + mt) * 4 + n) * 32 + lid;
                    zx4[zi] = make_float4(S1[mt][n][0] + S2[mt][n][0],
                                          S1[mt][n][1] + S2[mt][n][1],
                                          S1[mt][n][2] + S2[mt][n][2],
                                          S1[mt][n][3] + S2[mt][n][3]);
                }
        }
        __syncthreads();

        // ---- epilogue on kh==0 warps ----
        if (kh == 0) {
#pragma unroll
            for (int mt = 0; mt < 2; ++mt) {
                const int m = 2 * ms + mt;
                float zt[4][4];
#pragma unroll
                for (int n = 0; n < 4; ++n) {
                    int zi = ((ms * 2 + mt) * 4 + n) * 32 + lid;
                    float4 zp = zx4[zi];
                    zt[n][0] = S1[mt][n][0] + S2[mt][n][0] + zp.x;
                    zt[n][1] = S1[mt][n][1] + S2[mt][n][1] + zp.y;
                    zt[n][2] = S1[mt][n][2] + S2[mt][n][2] + zp.z;
                    zt[n][3] = S1[mt][n][3] + S2[mt][n][3] + zp.w;
                }
                const int blo = 16 * m + rq;
                float4 sLo = __ldg((const float4*)seq + ((size_t)blo * T + t));
                float4 sHi = __ldg((const float4*)seq + ((size_t)(blo + 8) * T + t));

                float hv4[4], cn4[4];
#pragma unroll
                for (int k = 0; k < 4; ++k) {
                    const int b  = blo + (k >> 1) * 8;
                    const int jj = jp + (k & 1);
                    const float4 sv = (k < 2) ? sLo : sHi;
                    float z[4];
#pragma unroll
                    for (int g = 0; g < 4; ++g) {
                        const int cc = g * 8 + jj;
                        z[g] = zt[g][k] + bsl[cc]
                             + sv.x * Wsl[cc] + sv.y * Wsl[32 + cc]
                             + sv.z * Wsl[64 + cc] + sv.w * Wsl[96 + cc];
                    }
                    float ig = 1.0f / (1.0f + __expf(-z[0]));
                    float fg = 1.0f / (1.0f + __expf(-z[1]));
                    float gg = fmaxf(z[2], 0.0f);
                    float og = 1.0f / (1.0f + __expf(-z[3]));
                    float cn = fg * c_reg[mt * 4 + k] + ig * gg;
                    c_reg[mt * 4 + k] = cn;
                    float hv = og * fmaxf(cn, 0.0f);
                    hv4[k] = hv; cn4[k] = cn;
                    out[((size_t)b * T + t) * H + j0 + jj] = hv;
                    if (write_extras && t == T - 1) {
                        out[OFF_HL + (size_t)b * H + j0 + jj] = hv;
                        out[OFF_CL + (size_t)b * H + j0 + jj] = cn;
                    }
                }
                // h-frag writeback: lane slot == lid; regs (codd*2, codd*2+1)
                __nv_bfloat16 h0 = __float2bfloat16(hv4[0]);
                __nv_bfloat16 h1 = __float2bfloat16(hv4[1]);
                __nv_bfloat16 h2 = __float2bfloat16(hv4[2]);
                __nv_bfloat16 h3 = __float2bfloat16(hv4[3]);
                __nv_bfloat16 l0 = __float2bfloat16(hv4[0] - __bfloat162float(h0));
                __nv_bfloat16 l1 = __float2bfloat16(hv4[1] - __bfloat162float(h1));
                __nv_bfloat16 l2 = __float2bfloat16(hv4[2] - __bfloat162float(h2));
                __nv_bfloat16 l3 = __float2bfloat16(hv4[3] - __bfloat162float(h3));
                int gidx = (Kc >> 2) * 1024 + (Kc & 3) * 256 + m * 32 + lid;
                ((uint2*)&g_hfH[wbuf][gidx])[codd] =
                    make_uint2(packbf(h0, h1), packbf(h2, h3));
                ((uint2*)&g_hfL[wbuf][gidx])[codd] =
                    make_uint2(packbf(l0, l1), packbf(l2, l3));
            }
        }
        grid_barrier();
    }
}

extern "C" void kernel_launch(void* const* d_in, const int* in_sizes, int n_in,
                              void* d_out, int out_size)
{
    const float* seq  = (const float*)d_in[0];   // [128,256,4]
    const float* W    = (const float*)d_in[1];   // [4,4096]
    const float* U    = (const float*)d_in[2];   // [1024,4096]
    const float* bias = (const float*)d_in[3];   // [4096]
    float* out = (float*)d_out;

    long long need = (long long)B * T * H + 2LL * B * H;
    int write_extras = ((long long)out_size >= need) ? 1 : 0;

    cudaFuncSetAttribute(lstm_frag_kernel,
                         cudaFuncAttributeMaxDynamicSharedMemorySize, SMEM_TOTAL);
    lstm_frag_kernel<<<CTAS, THREADS, SMEM_TOTAL>>>(seq, W, U, bias, out,
                                                    write_extras);
}

// round 6
// speedup vs baseline: 1.4599x; 1.3087x over previous
#include <cuda_runtime.h>
#include <cuda_bf16.h>
#include <cstdint>

#define B       128
#define T       256
#define H       1024
#define NG      4096
#define THREADS 256
#define CTAS    128
#define JPC     8
#define NCHUNK  16          // 16 chunks of k=64

// ---- persistent device state ----
// h in mma-A-fragment layout: [buf][chunk*1024 + qs*256 + m*32 + lane] (uint4 = a0..a3)
__device__ uint4 g_hfH[2][NCHUNK * 1024];
__device__ uint4 g_hfL[2][NCHUNK * 1024];
__device__ unsigned int g_bar_arrive = 0;
__device__ volatile unsigned int g_bar_gen = 0;

// ---- SMEM layout (bytes) ----
#define U_RSTRIDE 2064      // U^T rows padded -> conflict-free ldmatrix
#define OFF_UHI 0           // 66048
#define OFF_ULO 66048       // 66048
#define OFF_ZX  132096      // 16384  z exchange (k-half reduction)
#define OFF_W   148480      // 4*32 f32
#define OFF_BS  148992      // 32 f32
#define SMEM_TOTAL 149120

__device__ __forceinline__ uint32_t smem_u32(const void* p) {
    uint32_t a;
    asm("{ .reg .u64 t; cvta.to.shared.u64 t, %1; cvt.u32.u64 %0, t; }"
        : "=r"(a) : "l"(p));
    return a;
}

#define LDSM_X4(r0, r1, r2, r3, a) \
    asm volatile("ldmatrix.sync.aligned.m8n8.x4.shared.b16 {%0,%1,%2,%3}, [%4];" \
                 : "=r"(r0), "=r"(r1), "=r"(r2), "=r"(r3) : "r"(a))

#define MMA_BF16(d, a0, a1, a2, a3, b0, b1) \
    asm volatile("mma.sync.aligned.m16n8k16.row.col.f32.bf16.bf16.f32 " \
                 "{%0,%1,%2,%3}, {%4,%5,%6,%7}, {%8,%9}, {%0,%1,%2,%3};" \
                 : "+f"((d)[0]), "+f"((d)[1]), "+f"((d)[2]), "+f"((d)[3]) \
                 : "r"(a0), "r"(a1), "r"(a2), "r"(a3), "r"(b0), "r"(b1))

__device__ __forceinline__ void grid_barrier() {
    __syncthreads();
    __threadfence();
    if (threadIdx.x == 0) {
        unsigned int gen = g_bar_gen;
        if (atomicAdd(&g_bar_arrive, 1u) == CTAS - 1) {
            g_bar_arrive = 0;
            __threadfence();
            g_bar_gen = gen + 1;
        } else {
            while (g_bar_gen == gen) { }
        }
    }
    __syncthreads();
}

__device__ __forceinline__ uint32_t packbf(__nv_bfloat16 a, __nv_bfloat16 b) {
    return (uint32_t)__bfloat16_as_ushort(a) | ((uint32_t)__bfloat16_as_ushort(b) << 16);
}

// load this warp's 4 A-fragment pairs for chunk c straight from L2 into regs
__device__ __forceinline__ void ldfrags(uint4* rh, uint4* rl,
                                        const uint4* __restrict__ HH,
                                        const uint4* __restrict__ HL,
                                        int c, int kh2, int ms2, int lid) {
#pragma unroll
    for (int i = 0; i < 4; ++i) {
        const int q = i >> 1, mt = i & 1;
        const int idx = c * 1024 + (kh2 + q) * 256 + (ms2 + mt) * 32 + lid;
        rh[i] = __ldcg(HH + idx);
        rl[i] = __ldcg(HL + idx);
    }
}

__global__ void __launch_bounds__(THREADS, 1)
lstm_frag_kernel(const float* __restrict__ seq,
                 const float* __restrict__ W,
                 const float* __restrict__ U,
                 const float* __restrict__ bias,
                 float* __restrict__ out,
                 int write_extras)
{
    extern __shared__ __align__(1024) uint8_t smem[];
    const uint32_t sbase = smem_u32(smem);
    const int tid = threadIdx.x;
    const int wid = tid >> 5;
    const int lid = tid & 31;
    const int ms  = wid & 3;          // m-group: mtiles 2ms, 2ms+1
    const int kh  = wid >> 2;         // k-half of each chunk
    const int cta = blockIdx.x;
    const int j0  = cta * JPC;
    const int Kc  = cta >> 1;         // frag kstep this CTA's j-columns land in
    const int codd = cta & 1;

    float*  Wsl  = (float*)(smem + OFF_W);
    float*  bsl  = (float*)(smem + OFF_BS);
    float4* zx4  = (float4*)(smem + OFF_ZX);

    // ---------------- prologue ----------------
    // U slice -> U^T bf16 hi/lo (row n = gate*8+jj, k contiguous)
    for (int idx = tid; idx < 32 * H; idx += THREADS) {
        int k = idx >> 5, n = idx & 31;
        int gcol = ((n >> 3) << 10) + j0 + (n & 7);
        float v = U[(size_t)k * NG + gcol];
        __nv_bfloat16 hi = __float2bfloat16(v);
        __nv_bfloat16 lo = __float2bfloat16(v - __bfloat162float(hi));
        *(__nv_bfloat16*)(smem + OFF_UHI + n * U_RSTRIDE + k * 2) = hi;
        *(__nv_bfloat16*)(smem + OFF_ULO + n * U_RSTRIDE + k * 2) = lo;
    }
    if (tid < 4 * 32) {
        int f = tid >> 5, cc = tid & 31;
        Wsl[tid] = W[f * NG + ((cc >> 3) << 10) + j0 + (cc & 7)];
    }
    if (tid < 32)
        bsl[tid] = bias[((tid >> 3) << 10) + j0 + (tid & 7)];
    // zero-init this CTA's h-frag region in buf 0 (its 8B half of each elem)
    {
        int m = tid >> 5, lane = tid & 31;
        int gidx = (Kc >> 2) * 1024 + (Kc & 3) * 256 + m * 32 + lane;
        ((uint2*)&g_hfH[0][gidx])[codd] = make_uint2(0u, 0u);
        ((uint2*)&g_hfL[0][gidx])[codd] = make_uint2(0u, 0u);
    }
    grid_barrier();

    // ---- B ldmatrix lane geometry ----
    const int lr  = lid & 7;
    const int grp = lid >> 3;
    const uint32_t boff = (uint32_t)(((grp >> 1) * 8 + lr) * U_RSTRIDE + (grp & 1) * 16);
    const uint32_t uhib = sbase + OFF_UHI;
    const uint32_t ulob = sbase + OFF_ULO;

    const int rq = lid >> 2;
    const int jp = (lid & 3) * 2;
    const int kh2 = 2 * kh, ms2 = 2 * ms;

    float c_reg[8];
#pragma unroll
    for (int q = 0; q < 8; ++q) c_reg[q] = 0.0f;

    const size_t OFF_HL = (size_t)B * T * H;
    const size_t OFF_CL = OFF_HL + (size_t)B * H;

    for (int t = 0; t < T; ++t) {
        const int rb = t & 1, wbuf = rb ^ 1;
        const uint4* HH = g_hfH[rb];
        const uint4* HL = g_hfL[rb];

        // acc: S1 = Ah*Bh, S2 = Ah*Bl + Al*Bh  [mt][n][4]
        float S1[2][4][4], S2[2][4][4];
#pragma unroll
        for (int mt = 0; mt < 2; ++mt)
#pragma unroll
            for (int n = 0; n < 4; ++n)
#pragma unroll
                for (int r = 0; r < 4; ++r) { S1[mt][n][r] = 0.f; S2[mt][n][r] = 0.f; }

        // register double-buffer of A fragments; no SMEM, no syncs in GEMM
        uint4 rH[2][4], rL[2][4];
        ldfrags(rH[0], rL[0], HH, HL, 0, kh2, ms2, lid);

#pragma unroll 2
        for (int c = 0; c < NCHUNK; ++c) {
            const int cur = c & 1, nxt = cur ^ 1;
            if (c + 1 < NCHUNK)
                ldfrags(rH[nxt], rL[nxt], HH, HL, c + 1, kh2, ms2, lid);

#pragma unroll
            for (int q = 0; q < 2; ++q) {
                const int K = 4 * c + kh2 + q;     // global kstep
                uint32_t bh[8], bl[8];
                LDSM_X4(bh[0], bh[1], bh[2], bh[3], uhib + boff + (uint32_t)K * 32u);
                LDSM_X4(bh[4], bh[5], bh[6], bh[7], uhib + boff + 16u * U_RSTRIDE + (uint32_t)K * 32u);
                LDSM_X4(bl[0], bl[1], bl[2], bl[3], ulob + boff + (uint32_t)K * 32u);
                LDSM_X4(bl[4], bl[5], bl[6], bl[7], ulob + boff + 16u * U_RSTRIDE + (uint32_t)K * 32u);
#pragma unroll
                for (int mt = 0; mt < 2; ++mt) {
                    const uint4 AH = rH[cur][q * 2 + mt];
                    const uint4 AL = rL[cur][q * 2 + mt];
#pragma unroll
                    for (int n = 0; n < 4; ++n) {
                        MMA_BF16(S1[mt][n], AH.x, AH.y, AH.z, AH.w, bh[2 * n], bh[2 * n + 1]);
                        MMA_BF16(S2[mt][n], AH.x, AH.y, AH.z, AH.w, bl[2 * n], bl[2 * n + 1]);
                        MMA_BF16(S2[mt][n], AL.x, AL.y, AL.z, AL.w, bh[2 * n], bh[2 * n + 1]);
                    }
                }
            }
        }

        // ---- reduce the two k-halves ----
        if (kh == 1) {
#pragma unroll
            for (int mt = 0; mt < 2; ++mt)
#pragma unroll
                for (int n = 0; n < 4; ++n) {
                    int zi = ((ms * 2 + mt) * 4 + n) * 32 + lid;
                    zx4[zi] = make_float4(S1[mt][n][0] + S2[mt][n][0],
                                          S1[mt][n][1] + S2[mt][n][1],
                                          S1[mt][n][2] + S2[mt][n][2],
                                          S1[mt][n][3] + S2[mt][n][3]);
                }
        }
        __syncthreads();

        // ---- epilogue on kh==0 warps ----
        if (kh == 0) {
#pragma unroll
            for (int mt = 0; mt < 2; ++mt) {
                const int m = ms2 + mt;
                float zt[4][4];
#pragma unroll
                for (int n = 0; n < 4; ++n) {
                    int zi = ((ms * 2 + mt) * 4 + n) * 32 + lid;
                    float4 zp = zx4[zi];
                    zt[n][0] = S1[mt][n][0] + S2[mt][n][0] + zp.x;
                    zt[n][1] = S1[mt][n][1] + S2[mt][n][1] + zp.y;
                    zt[n][2] = S1[mt][n][2] + S2[mt][n][2] + zp.z;
                    zt[n][3] = S1[mt][n][3] + S2[mt][n][3] + zp.w;
                }
                const int blo = 16 * m + rq;
                float4 sLo = __ldg((const float4*)seq + ((size_t)blo * T + t));
                float4 sHi = __ldg((const float4*)seq + ((size_t)(blo + 8) * T + t));

                float hv4[4];
#pragma unroll
                for (int k = 0; k < 4; ++k) {
                    const int b  = blo + (k >> 1) * 8;
                    const int jj = jp + (k & 1);
                    const float4 sv = (k < 2) ? sLo : sHi;
                    float z[4];
#pragma unroll
                    for (int g = 0; g < 4; ++g) {
                        const int cc = g * 8 + jj;
                        z[g] = zt[g][k] + bsl[cc]
                             + sv.x * Wsl[cc] + sv.y * Wsl[32 + cc]
                             + sv.z * Wsl[64 + cc] + sv.w * Wsl[96 + cc];
                    }
                    float ig = 1.0f / (1.0f + __expf(-z[0]));
                    float fg = 1.0f / (1.0f + __expf(-z[1]));
                    float gg = fmaxf(z[2], 0.0f);
                    float og = 1.0f / (1.0f + __expf(-z[3]));
                    float cn = fg * c_reg[mt * 4 + k] + ig * gg;
                    c_reg[mt * 4 + k] = cn;
                    float hv = og * fmaxf(cn, 0.0f);
                    hv4[k] = hv;
                    out[((size_t)b * T + t) * H + j0 + jj] = hv;
                    if (write_extras && t == T - 1) {
                        out[OFF_HL + (size_t)b * H + j0 + jj] = hv;
                        out[OFF_CL + (size_t)b * H + j0 + jj] = cn;
                    }
                }
                // h-frag writeback (lane slot == lid; 8B half selected by codd)
                __nv_bfloat16 h0 = __float2bfloat16(hv4[0]);
                __nv_bfloat16 h1 = __float2bfloat16(hv4[1]);
                __nv_bfloat16 h2 = __float2bfloat16(hv4[2]);
                __nv_bfloat16 h3 = __float2bfloat16(hv4[3]);
                __nv_bfloat16 l0 = __float2bfloat16(hv4[0] - __bfloat162float(h0));
                __nv_bfloat16 l1 = __float2bfloat16(hv4[1] - __bfloat162float(h1));
                __nv_bfloat16 l2 = __float2bfloat16(hv4[2] - __bfloat162float(h2));
                __nv_bfloat16 l3 = __float2bfloat16(hv4[3] - __bfloat162float(h3));
                int gidx = (Kc >> 2) * 1024 + (Kc & 3) * 256 + m * 32 + lid;
                ((uint2*)&g_hfH[wbuf][gidx])[codd] =
                    make_uint2(packbf(h0, h1), packbf(h2, h3));
                ((uint2*)&g_hfL[wbuf][gidx])[codd] =
                    make_uint2(packbf(l0, l1), packbf(l2, l3));
            }
        }
        grid_barrier();
    }
}

extern "C" void kernel_launch(void* const* d_in, const int* in_sizes, int n_in,
                              void* d_out, int out_size)
{
    const float* seq  = (const float*)d_in[0];   // [128,256,4]
    const float* W    = (const float*)d_in[1];   // [4,4096]
    const float* U    = (const float*)d_in[2];   // [1024,4096]
    const float* bias = (const float*)d_in[3];   // [4096]
    float* out = (float*)d_out;

    long long need = (long long)B * T * H + 2LL * B * H;
    int write_extras = ((long long)out_size >= need) ? 1 : 0;

    cudaFuncSetAttribute(lstm_frag_kernel,
                         cudaFuncAttributeMaxDynamicSharedMemorySize, SMEM_TOTAL);
    lstm_frag_kernel<<<CTAS, THREADS, SMEM_TOTAL>>>(seq, W, U, bias, out,
                                                    write_extras);
}

// round 7
// speedup vs baseline: 1.5384x; 1.0538x over previous
#include <cuda_runtime.h>
#include <cuda_bf16.h>
#include <cstdint>

#define B       128
#define T       256
#define H       1024
#define NG      4096
#define THREADS 512
#define CTAS    128
#define JPC     8
#define NCHUNK  16          // 16 chunks of k=64

// ---- persistent device state ----
// h in mma-A-fragment layout: [buf][chunk*1024 + qs*256 + m*32 + lane] (uint4)
__device__ uint4 g_hfH[2][NCHUNK * 1024];
__device__ uint4 g_hfL[2][NCHUNK * 1024];
__device__ unsigned int g_bar_arrive = 0;
__device__ volatile unsigned int g_bar_gen = 0;

// ---- SMEM layout (bytes) ----
#define U_RSTRIDE 2064      // U^T rows padded -> conflict-free ldmatrix
#define OFF_UHI 0           // 66048
#define OFF_ULO 66048       // 66048
#define OFF_ZX  132096      // 16384  z exchange (k-half reduction)
#define OFF_W   148480      // 4*32 f32
#define OFF_BS  148992      // 32 f32
#define SMEM_TOTAL 149120

__device__ __forceinline__ uint32_t smem_u32(const void* p) {
    uint32_t a;
    asm("{ .reg .u64 t; cvta.to.shared.u64 t, %1; cvt.u32.u64 %0, t; }"
        : "=r"(a) : "l"(p));
    return a;
}

#define LDSM_X4(r0, r1, r2, r3, a) \
    asm volatile("ldmatrix.sync.aligned.m8n8.x4.shared.b16 {%0,%1,%2,%3}, [%4];" \
                 : "=r"(r0), "=r"(r1), "=r"(r2), "=r"(r3) : "r"(a))

#define MMA_BF16(d, a0, a1, a2, a3, b0, b1) \
    asm volatile("mma.sync.aligned.m16n8k16.row.col.f32.bf16.bf16.f32 " \
                 "{%0,%1,%2,%3}, {%4,%5,%6,%7}, {%8,%9}, {%0,%1,%2,%3};" \
                 : "+f"((d)[0]), "+f"((d)[1]), "+f"((d)[2]), "+f"((d)[3]) \
                 : "r"(a0), "r"(a1), "r"(a2), "r"(a3), "r"(b0), "r"(b1))

__device__ __forceinline__ void grid_barrier() {
    __syncthreads();
    __threadfence();
    if (threadIdx.x == 0) {
        unsigned int gen = g_bar_gen;
        if (atomicAdd(&g_bar_arrive, 1u) == CTAS - 1) {
            g_bar_arrive = 0;
            __threadfence();
            g_bar_gen = gen + 1;
        } else {
            while (g_bar_gen == gen) { }
        }
    }
    __syncthreads();
}

__device__ __forceinline__ uint32_t packbf(__nv_bfloat16 a, __nv_bfloat16 b) {
    return (uint32_t)__bfloat16_as_ushort(a) | ((uint32_t)__bfloat16_as_ushort(b) << 16);
}

// load this warp's 2 A-fragment pairs (q=0,1) for chunk c from L2 into regs
__device__ __forceinline__ void ldfrags(uint4* rh, uint4* rl,
                                        const uint4* __restrict__ HH,
                                        const uint4* __restrict__ HL,
                                        int c, int kh2, int m, int lid) {
#pragma unroll
    for (int q = 0; q < 2; ++q) {
        const int idx = c * 1024 + (kh2 + q) * 256 + m * 32 + lid;
        rh[q] = __ldcg(HH + idx);
        rl[q] = __ldcg(HL + idx);
    }
}

__global__ void __launch_bounds__(THREADS, 1)
lstm_frag_kernel(const float* __restrict__ seq,
                 const float* __restrict__ W,
                 const float* __restrict__ U,
                 const float* __restrict__ bias,
                 float* __restrict__ out,
                 int write_extras)
{
    extern __shared__ __align__(1024) uint8_t smem[];
    const uint32_t sbase = smem_u32(smem);
    const int tid = threadIdx.x;
    const int wid = tid >> 5;
    const int lid = tid & 31;
    const int m   = wid & 7;          // m-tile 0..7 (16 batch rows each)
    const int kh  = wid >> 3;         // k-half of each chunk
    const int cta = blockIdx.x;
    const int j0  = cta * JPC;
    const int Kc  = cta >> 1;         // frag kstep this CTA's j-columns land in
    const int codd = cta & 1;

    float*  Wsl  = (float*)(smem + OFF_W);
    float*  bsl  = (float*)(smem + OFF_BS);
    float4* zx4  = (float4*)(smem + OFF_ZX);

    // ---------------- prologue ----------------
    // U slice -> U^T bf16 hi/lo (row n = gate*8+jj, k contiguous)
    for (int idx = tid; idx < 32 * H; idx += THREADS) {
        int k = idx >> 5, n = idx & 31;
        int gcol = ((n >> 3) << 10) + j0 + (n & 7);
        float v = U[(size_t)k * NG + gcol];
        __nv_bfloat16 hi = __float2bfloat16(v);
        __nv_bfloat16 lo = __float2bfloat16(v - __bfloat162float(hi));
        *(__nv_bfloat16*)(smem + OFF_UHI + n * U_RSTRIDE + k * 2) = hi;
        *(__nv_bfloat16*)(smem + OFF_ULO + n * U_RSTRIDE + k * 2) = lo;
    }
    if (tid < 4 * 32) {
        int f = tid >> 5, cc = tid & 31;
        Wsl[tid] = W[f * NG + ((cc >> 3) << 10) + j0 + (cc & 7)];
    }
    if (tid < 32)
        bsl[tid] = bias[((tid >> 3) << 10) + j0 + (tid & 7)];
    // zero-init this CTA's h-frag region in buf 0 (its 8B half of each elem)
    if (tid < 256) {
        int mm = tid >> 5, lane = tid & 31;
        int gidx = (Kc >> 2) * 1024 + (Kc & 3) * 256 + mm * 32 + lane;
        ((uint2*)&g_hfH[0][gidx])[codd] = make_uint2(0u, 0u);
        ((uint2*)&g_hfL[0][gidx])[codd] = make_uint2(0u, 0u);
    }
    grid_barrier();

    // ---- B ldmatrix lane geometry ----
    const int lr  = lid & 7;
    const int grp = lid >> 3;
    const uint32_t boff = (uint32_t)(((grp >> 1) * 8 + lr) * U_RSTRIDE + (grp & 1) * 16);
    const uint32_t uhib = sbase + OFF_UHI;
    const uint32_t ulob = sbase + OFF_ULO;

    const int rq = lid >> 2;
    const int jp = (lid & 3) * 2;
    const int kh2 = 2 * kh;

    float c_reg[4];
#pragma unroll
    for (int q = 0; q < 4; ++q) c_reg[q] = 0.0f;

    const size_t OFF_HL = (size_t)B * T * H;
    const size_t OFF_CL = OFF_HL + (size_t)B * H;

    for (int t = 0; t < T; ++t) {
        const int rb = t & 1, wbuf = rb ^ 1;
        const uint4* HH = g_hfH[rb];
        const uint4* HL = g_hfL[rb];

        // acc: S1 = Ah*Bh, S2 = Ah*Bl + Al*Bh  [n][4]
        float S1[4][4], S2[4][4];
#pragma unroll
        for (int n = 0; n < 4; ++n)
#pragma unroll
            for (int r = 0; r < 4; ++r) { S1[n][r] = 0.f; S2[n][r] = 0.f; }

        // register double-buffer of A fragments; no syncs in GEMM
        uint4 rH[2][2], rL[2][2];
        ldfrags(rH[0], rL[0], HH, HL, 0, kh2, m, lid);

#pragma unroll 2
        for (int c = 0; c < NCHUNK; ++c) {
            const int cur = c & 1, nxt = cur ^ 1;
            if (c + 1 < NCHUNK)
                ldfrags(rH[nxt], rL[nxt], HH, HL, c + 1, kh2, m, lid);

#pragma unroll
            for (int q = 0; q < 2; ++q) {
                const int K = 4 * c + kh2 + q;     // global kstep
                uint32_t bh[8], bl[8];
                LDSM_X4(bh[0], bh[1], bh[2], bh[3], uhib + boff + (uint32_t)K * 32u);
                LDSM_X4(bh[4], bh[5], bh[6], bh[7], uhib + boff + 16u * U_RSTRIDE + (uint32_t)K * 32u);
                LDSM_X4(bl[0], bl[1], bl[2], bl[3], ulob + boff + (uint32_t)K * 32u);
                LDSM_X4(bl[4], bl[5], bl[6], bl[7], ulob + boff + 16u * U_RSTRIDE + (uint32_t)K * 32u);
                const uint4 AH = rH[cur][q];
                const uint4 AL = rL[cur][q];
#pragma unroll
                for (int n = 0; n < 4; ++n) {
                    MMA_BF16(S1[n], AH.x, AH.y, AH.z, AH.w, bh[2 * n], bh[2 * n + 1]);
                    MMA_BF16(S2[n], AH.x, AH.y, AH.z, AH.w, bl[2 * n], bl[2 * n + 1]);
                    MMA_BF16(S2[n], AL.x, AL.y, AL.z, AL.w, bh[2 * n], bh[2 * n + 1]);
                }
            }
        }

        // ---- reduce the two k-halves ----
        if (kh == 1) {
#pragma unroll
            for (int n = 0; n < 4; ++n) {
                int zi = (m * 4 + n) * 32 + lid;
                zx4[zi] = make_float4(S1[n][0] + S2[n][0],
                                      S1[n][1] + S2[n][1],
                                      S1[n][2] + S2[n][2],
                                      S1[n][3] + S2[n][3]);
            }
        }
        __syncthreads();

        // ---- epilogue on kh==0 warps (one m-tile each) ----
        if (kh == 0) {
            float zt[4][4];
#pragma unroll
            for (int n = 0; n < 4; ++n) {
                int zi = (m * 4 + n) * 32 + lid;
                float4 zp = zx4[zi];
                zt[n][0] = S1[n][0] + S2[n][0] + zp.x;
                zt[n][1] = S1[n][1] + S2[n][1] + zp.y;
                zt[n][2] = S1[n][2] + S2[n][2] + zp.z;
                zt[n][3] = S1[n][3] + S2[n][3] + zp.w;
            }
            const int blo = 16 * m + rq;
            float4 sLo = __ldg((const float4*)seq + ((size_t)blo * T + t));
            float4 sHi = __ldg((const float4*)seq + ((size_t)(blo + 8) * T + t));

            float hv4[4];
#pragma unroll
            for (int k = 0; k < 4; ++k) {
                const int b  = blo + (k >> 1) * 8;
                const int jj = jp + (k & 1);
                const float4 sv = (k < 2) ? sLo : sHi;
                float z[4];
#pragma unroll
                for (int g = 0; g < 4; ++g) {
                    const int cc = g * 8 + jj;
                    z[g] = zt[g][k] + bsl[cc]
                         + sv.x * Wsl[cc] + sv.y * Wsl[32 + cc]
                         + sv.z * Wsl[64 + cc] + sv.w * Wsl[96 + cc];
                }
                float ig = 1.0f / (1.0f + __expf(-z[0]));
                float fg = 1.0f / (1.0f + __expf(-z[1]));
                float gg = fmaxf(z[2], 0.0f);
                float og = 1.0f / (1.0f + __expf(-z[3]));
                float cn = fg * c_reg[k] + ig * gg;
                c_reg[k] = cn;
                float hv = og * fmaxf(cn, 0.0f);
                hv4[k] = hv;
                out[((size_t)b * T + t) * H + j0 + jj] = hv;
                if (write_extras && t == T - 1) {
                    out[OFF_HL + (size_t)b * H + j0 + jj] = hv;
                    out[OFF_CL + (size_t)b * H + j0 + jj] = cn;
                }
            }
            // h-frag writeback (lane slot == lid; 8B half selected by codd)
            __nv_bfloat16 h0 = __float2bfloat16(hv4[0]);
            __nv_bfloat16 h1 = __float2bfloat16(hv4[1]);
            __nv_bfloat16 h2 = __float2bfloat16(hv4[2]);
            __nv_bfloat16 h3 = __float2bfloat16(hv4[3]);
            __nv_bfloat16 l0 = __float2bfloat16(hv4[0] - __bfloat162float(h0));
            __nv_bfloat16 l1 = __float2bfloat16(hv4[1] - __bfloat162float(h1));
            __nv_bfloat16 l2 = __float2bfloat16(hv4[2] - __bfloat162float(h2));
            __nv_bfloat16 l3 = __float2bfloat16(hv4[3] - __bfloat162float(h3));
            int gidx = (Kc >> 2) * 1024 + (Kc & 3) * 256 + m * 32 + lid;
            ((uint2*)&g_hfH[wbuf][gidx])[codd] =
                make_uint2(packbf(h0, h1), packbf(h2, h3));
            ((uint2*)&g_hfL[wbuf][gidx])[codd] =
                make_uint2(packbf(l0, l1), packbf(l2, l3));
        }
        grid_barrier();
    }
}

extern "C" void kernel_launch(void* const* d_in, const int* in_sizes, int n_in,
                              void* d_out, int out_size)
{
    const float* seq  = (const float*)d_in[0];   // [128,256,4]
    const float* W    = (const float*)d_in[1];   // [4,4096]
    const float* U    = (const float*)d_in[2];   // [1024,4096]
    const float* bias = (const float*)d_in[3];   // [4096]
    float* out = (float*)d_out;

    long long need = (long long)B * T * H + 2LL * B * H;
    int write_extras = ((long long)out_size >= need) ? 1 : 0;

    cudaFuncSetAttribute(lstm_frag_kernel,
                         cudaFuncAttributeMaxDynamicSharedMemorySize, SMEM_TOTAL);
    lstm_frag_kernel<<<CTAS, THREADS, SMEM_TOTAL>>>(seq, W, U, bias, out,
                                                    write_extras);
}